// round 1
// baseline (speedup 1.0000x reference)
#include <cuda_runtime.h>
#include <cuda_bf16.h>
#include <mma.h>
#include <cstdint>
#include <cstddef>

using namespace nvcuda;

#define T_STEPS 512
#define B_SZ    128
#define E_SEQ   768
#define COND    256
#define H_DIM   1024
#define KIN     1024      // COND + E_SEQ
#define G3      3072      // 3*H

// ---------------- scratch (static device globals; no allocation) -------------
__device__ float          g_gx[(size_t)T_STEPS * B_SZ * G3];   // 805 MB, fp32 gate pre-activations (input side)
__device__ float          g_h[2][B_SZ * H_DIM];                // double-buffered hidden state
__device__ __nv_bfloat16  g_whh_hi[(size_t)G3 * H_DIM];
__device__ __nv_bfloat16  g_whh_lo[(size_t)G3 * H_DIM];

// ---------------- prep kernels ----------------------------------------------
__global__ void k_split_whh(const float* __restrict__ whh) {
    int i = blockIdx.x * blockDim.x + threadIdx.x;
    if (i < G3 * H_DIM) {
        float v = whh[i];
        __nv_bfloat16 hi = __float2bfloat16(v);
        g_whh_hi[i] = hi;
        g_whh_lo[i] = __float2bfloat16(v - __bfloat162float(hi));
    }
}

__global__ void k_init_h(const float* __restrict__ h0) {
    int i = blockIdx.x * blockDim.x + threadIdx.x;
    if (i < B_SZ * H_DIM) g_h[0][i] = h0[i];
}

// ---------------- gx GEMM: gx[m,n] = sum_k concat(word,seq)[m,k] * W_ih[n,k] --
// bf16x2 split (hi*hi + hi*lo + lo*hi), fp32 accumulate. Bias b_ih is added
// later in the gating kernel, so this is a pure GEMM.
#define BM 128
#define BN 128
#define BKK 32
#define PLD 40   // padded smem leading dim (bf16 elems), 80B = mult of 16B

__global__ __launch_bounds__(256) void k_gx_gemm(
        const float* __restrict__ seq,   // [T*B, 768]
        const float* __restrict__ word,  // [B, 256]
        const float* __restrict__ wih)   // [3072, 1024]
{
    __shared__ __align__(16) __nv_bfloat16 As_hi[BM][PLD];
    __shared__ __align__(16) __nv_bfloat16 As_lo[BM][PLD];
    __shared__ __align__(16) __nv_bfloat16 Bs_hi[BN][PLD];
    __shared__ __align__(16) __nv_bfloat16 Bs_lo[BN][PLD];

    const int tid = threadIdx.x;
    const int m0  = blockIdx.x * BM;
    const int n0  = blockIdx.y * BN;

    const int wid = tid >> 5;
    const int wm  = wid & 3;          // 4 warp rows (32 m each)
    const int wn  = wid >> 2;         // 2 warp cols (64 n each)

    wmma::fragment<wmma::accumulator, 16, 16, 16, float> acc[2][4];
    #pragma unroll
    for (int i = 0; i < 2; i++)
        #pragma unroll
        for (int j = 0; j < 4; j++) wmma::fill_fragment(acc[i][j], 0.0f);

    const int lk = tid & 31;          // k within chunk
    const int lr = tid >> 5;          // 0..7

    for (int k0 = 0; k0 < KIN; k0 += BKK) {
        const int kk = k0 + lk;
        // A tile: concat(word, seq) rows m0..m0+127
        #pragma unroll
        for (int it = 0; it < 16; it++) {
            int row = lr + it * 8;
            int m = m0 + row;
            float v = (kk < COND)
                    ? word[(m & (B_SZ - 1)) * COND + kk]
                    : seq[(size_t)m * E_SEQ + (kk - COND)];
            __nv_bfloat16 hi = __float2bfloat16(v);
            As_hi[row][lk] = hi;
            As_lo[row][lk] = __float2bfloat16(v - __bfloat162float(hi));
        }
        // B tile: W_ih rows n0..n0+127
        #pragma unroll
        for (int it = 0; it < 16; it++) {
            int row = lr + it * 8;
            float v = wih[(size_t)(n0 + row) * KIN + kk];
            __nv_bfloat16 hi = __float2bfloat16(v);
            Bs_hi[row][lk] = hi;
            Bs_lo[row][lk] = __float2bfloat16(v - __bfloat162float(hi));
        }
        __syncthreads();

        #pragma unroll
        for (int ks = 0; ks < BKK; ks += 16) {
            wmma::fragment<wmma::matrix_a, 16, 16, 16, __nv_bfloat16, wmma::row_major> a_hi[2], a_lo[2];
            #pragma unroll
            for (int i = 0; i < 2; i++) {
                wmma::load_matrix_sync(a_hi[i], &As_hi[wm * 32 + i * 16][ks], PLD);
                wmma::load_matrix_sync(a_lo[i], &As_lo[wm * 32 + i * 16][ks], PLD);
            }
            #pragma unroll
            for (int j = 0; j < 4; j++) {
                wmma::fragment<wmma::matrix_b, 16, 16, 16, __nv_bfloat16, wmma::col_major> b_hi, b_lo;
                wmma::load_matrix_sync(b_hi, &Bs_hi[wn * 64 + j * 16][ks], PLD);
                wmma::load_matrix_sync(b_lo, &Bs_lo[wn * 64 + j * 16][ks], PLD);
                #pragma unroll
                for (int i = 0; i < 2; i++) {
                    wmma::mma_sync(acc[i][j], a_hi[i], b_hi, acc[i][j]);
                    wmma::mma_sync(acc[i][j], a_hi[i], b_lo, acc[i][j]);
                    wmma::mma_sync(acc[i][j], a_lo[i], b_hi, acc[i][j]);
                }
            }
        }
        __syncthreads();
    }

    #pragma unroll
    for (int i = 0; i < 2; i++)
        #pragma unroll
        for (int j = 0; j < 4; j++) {
            size_t m = (size_t)m0 + wm * 32 + i * 16;
            size_t n = (size_t)n0 + wn * 64 + j * 16;
            wmma::store_matrix_sync(&g_gx[m * G3 + n], acc[i][j], G3, wmma::mem_row_major);
        }
}

// ---------------- GRU step: gh = h @ W_hh^T (split bf16x2) + fused gating ----
// grid (4, 32): block owns b-tile of 32 x j-tile of 32, computes all 3 gates.
__global__ __launch_bounds__(192) void k_gru_step(
        int t,
        const float* __restrict__ bih,
        const float* __restrict__ bhh,
        float* __restrict__ out,
        int write_hidden)
{
    __shared__ __align__(16) __nv_bfloat16 hs_hi[32][PLD], hs_lo[32][PLD];
    __shared__ __align__(16) __nv_bfloat16 ws_hi[3][32][PLD], ws_lo[3][32][PLD];
    __shared__ __align__(16) float gh_s[3][32][32];

    const float* __restrict__ h_prev = g_h[t & 1];
    float* __restrict__ h_next       = g_h[(t + 1) & 1];
    const float* __restrict__ gx_t   = g_gx + (size_t)t * B_SZ * G3;

    const int tid = threadIdx.x;      // 192 threads = 6 warps
    const int b0  = blockIdx.x * 32;
    const int j0  = blockIdx.y * 32;
    const int wid = tid >> 5;         // 0..5
    const int g   = wid >> 1;         // gate 0..2
    const int m0  = (wid & 1) * 16;   // b-half

    wmma::fragment<wmma::accumulator, 16, 16, 16, float> acc[2];
    wmma::fill_fragment(acc[0], 0.0f);
    wmma::fill_fragment(acc[1], 0.0f);

    for (int k0 = 0; k0 < H_DIM; k0 += 32) {
        // h tile 32x32, split on the fly
        for (int idx = tid; idx < 32 * 32; idx += 192) {
            int r = idx >> 5, k = idx & 31;
            float v = h_prev[(size_t)(b0 + r) * H_DIM + k0 + k];
            __nv_bfloat16 hi = __float2bfloat16(v);
            hs_hi[r][k] = hi;
            hs_lo[r][k] = __float2bfloat16(v - __bfloat162float(hi));
        }
        // W_hh tiles for 3 gates, pre-split in global
        for (int idx = tid; idx < 3 * 32 * 32; idx += 192) {
            int gg = idx >> 10;
            int r  = (idx >> 5) & 31;
            int k  = idx & 31;
            size_t off = (size_t)(gg * H_DIM + j0 + r) * H_DIM + k0 + k;
            ws_hi[gg][r][k] = g_whh_hi[off];
            ws_lo[gg][r][k] = g_whh_lo[off];
        }
        __syncthreads();

        #pragma unroll
        for (int ks = 0; ks < 32; ks += 16) {
            wmma::fragment<wmma::matrix_a, 16, 16, 16, __nv_bfloat16, wmma::row_major> a_hi, a_lo;
            wmma::load_matrix_sync(a_hi, &hs_hi[m0][ks], PLD);
            wmma::load_matrix_sync(a_lo, &hs_lo[m0][ks], PLD);
            #pragma unroll
            for (int nf = 0; nf < 2; nf++) {
                wmma::fragment<wmma::matrix_b, 16, 16, 16, __nv_bfloat16, wmma::col_major> b_hi, b_lo;
                wmma::load_matrix_sync(b_hi, &ws_hi[g][nf * 16][ks], PLD);
                wmma::load_matrix_sync(b_lo, &ws_lo[g][nf * 16][ks], PLD);
                wmma::mma_sync(acc[nf], a_hi, b_hi, acc[nf]);
                wmma::mma_sync(acc[nf], a_hi, b_lo, acc[nf]);
                wmma::mma_sync(acc[nf], a_lo, b_hi, acc[nf]);
            }
        }
        __syncthreads();
    }

    wmma::store_matrix_sync(&gh_s[g][m0][0],  acc[0], 32, wmma::mem_row_major);
    wmma::store_matrix_sync(&gh_s[g][m0][16], acc[1], 32, wmma::mem_row_major);
    __syncthreads();

    // fused gating + state update + output write
    for (int idx = tid; idx < 32 * 32; idx += 192) {
        int bl = idx >> 5, jl = idx & 31;
        int b = b0 + bl, j = j0 + jl;
        size_t gb = (size_t)b * G3;
        float xr = gx_t[gb + j]             + bih[j];
        float xz = gx_t[gb + H_DIM + j]     + bih[H_DIM + j];
        float xn = gx_t[gb + 2 * H_DIM + j] + bih[2 * H_DIM + j];
        float hr = gh_s[0][bl][jl] + bhh[j];
        float hz = gh_s[1][bl][jl] + bhh[H_DIM + j];
        float hn = gh_s[2][bl][jl] + bhh[2 * H_DIM + j];
        float r = 1.0f / (1.0f + expf(-(xr + hr)));
        float z = 1.0f / (1.0f + expf(-(xz + hz)));
        float n = tanhf(xn + r * hn);
        float hp = h_prev[(size_t)b * H_DIM + j];
        float h = (1.0f - z) * n + z * hp;
        h_next[(size_t)b * H_DIM + j] = h;
        out[((size_t)t * B_SZ + b) * H_DIM + j] = h;
        if (write_hidden)
            out[(size_t)T_STEPS * B_SZ * H_DIM + (size_t)b * H_DIM + j] = h;
    }
}

// ---------------- launch ------------------------------------------------------
extern "C" void kernel_launch(void* const* d_in, const int* in_sizes, int n_in,
                              void* d_out, int out_size) {
    const float* seq  = (const float*)d_in[0];  // [512,128,768]
    const float* word = (const float*)d_in[1];  // [128,256]
    const float* h0   = (const float*)d_in[2];  // [1,128,1024]
    const float* wih  = (const float*)d_in[3];  // [3072,1024]
    const float* whh  = (const float*)d_in[4];  // [3072,1024]
    const float* bih  = (const float*)d_in[5];  // [3072]
    const float* bhh  = (const float*)d_in[6];  // [3072]
    float* out = (float*)d_out;

    (void)in_sizes; (void)n_in;

    const int hidden_ok = (out_size >= T_STEPS * B_SZ * H_DIM + B_SZ * H_DIM) ? 1 : 0;

    k_split_whh<<<(G3 * H_DIM + 255) / 256, 256>>>(whh);
    k_init_h<<<(B_SZ * H_DIM + 255) / 256, 256>>>(h0);

    k_gx_gemm<<<dim3((T_STEPS * B_SZ) / BM, G3 / BN), 256>>>(seq, word, wih);

    for (int t = 0; t < T_STEPS; t++) {
        int wh = (t == T_STEPS - 1) ? hidden_ok : 0;
        k_gru_step<<<dim3(B_SZ / 32, H_DIM / 32), 192>>>(t, bih, bhh, out, wh);
    }
}

// round 2
// speedup vs baseline: 4.1067x; 4.1067x over previous
#include <cuda_runtime.h>
#include <cuda_bf16.h>
#include <mma.h>
#include <cstdint>
#include <cstddef>

using namespace nvcuda;

#define T_STEPS 512
#define B_SZ    128
#define E_SEQ   768
#define COND    256
#define H_DIM   1024
#define KIN     1024
#define G3      3072
#define M_TOT   (T_STEPS * B_SZ)
#define NBLK    128          // persistent grid size (< 148 SMs -> co-resident)

// ---------------- static device scratch --------------------------------------
__device__ float          g_gx[(size_t)M_TOT * G3];            // fp32 input-side gate preacts
__device__ __nv_bfloat16  g_whh_hi[(size_t)G3 * H_DIM];
__device__ __nv_bfloat16  g_whh_lo[(size_t)G3 * H_DIM];
__device__ __nv_bfloat16  g_wih_hi[(size_t)G3 * KIN];
__device__ __nv_bfloat16  g_wih_lo[(size_t)G3 * KIN];
__device__ __nv_bfloat16  g_xhi[(size_t)M_TOT * KIN];
__device__ __nv_bfloat16  g_xlo[(size_t)M_TOT * KIN];
__device__ __nv_bfloat16  g_hhi[2][B_SZ * H_DIM];              // double-buffered split h
__device__ __nv_bfloat16  g_hlo[2][B_SZ * H_DIM];
__device__ unsigned       g_count;                             // grid barrier counter

// ---------------- prep kernels ------------------------------------------------
__global__ void k_init() { if (threadIdx.x == 0 && blockIdx.x == 0) g_count = 0; }

__global__ void k_split_whh(const float* __restrict__ w) {
    int i = blockIdx.x * blockDim.x + threadIdx.x;
    if (i < G3 * H_DIM) {
        float v = w[i];
        __nv_bfloat16 hi = __float2bfloat16(v);
        g_whh_hi[i] = hi;
        g_whh_lo[i] = __float2bfloat16(v - __bfloat162float(hi));
    }
}
__global__ void k_split_wih(const float* __restrict__ w) {
    int i = blockIdx.x * blockDim.x + threadIdx.x;
    if (i < G3 * KIN) {
        float v = w[i];
        __nv_bfloat16 hi = __float2bfloat16(v);
        g_wih_hi[i] = hi;
        g_wih_lo[i] = __float2bfloat16(v - __bfloat162float(hi));
    }
}

// split concat(word, seq) into bf16 hi/lo, 4 elements per thread
__global__ void k_split_x(const float* __restrict__ seq, const float* __restrict__ word) {
    size_t i = (size_t)blockIdx.x * blockDim.x + threadIdx.x;   // over M_TOT*KIN/4
    if (i >= (size_t)M_TOT * KIN / 4) return;
    int m  = (int)(i >> 8);         // row (1024/4 = 256 quads per row)
    int kq = (int)(i & 255);
    float4 v;
    if (kq < 64) v = ((const float4*)word)[(m & (B_SZ - 1)) * 64 + kq];
    else         v = ((const float4*)seq)[(size_t)m * 192 + (kq - 64)];
    float f[4] = {v.x, v.y, v.z, v.w};
    __nv_bfloat162 ph0, ph1, pl0, pl1;
    ph0.x = __float2bfloat16(f[0]); ph0.y = __float2bfloat16(f[1]);
    ph1.x = __float2bfloat16(f[2]); ph1.y = __float2bfloat16(f[3]);
    pl0.x = __float2bfloat16(f[0] - __bfloat162float(ph0.x));
    pl0.y = __float2bfloat16(f[1] - __bfloat162float(ph0.y));
    pl1.x = __float2bfloat16(f[2] - __bfloat162float(ph1.x));
    pl1.y = __float2bfloat16(f[3] - __bfloat162float(ph1.y));
    ((__nv_bfloat162*)g_xhi)[2 * i]     = ph0;
    ((__nv_bfloat162*)g_xhi)[2 * i + 1] = ph1;
    ((__nv_bfloat162*)g_xlo)[2 * i]     = pl0;
    ((__nv_bfloat162*)g_xlo)[2 * i + 1] = pl1;
}

// ---------------- cp.async helpers -------------------------------------------
__device__ __forceinline__ void cp16(void* dst, const void* src) {
    unsigned d = (unsigned)__cvta_generic_to_shared(dst);
    asm volatile("cp.async.cg.shared.global [%0], [%1], 16;\n" :: "r"(d), "l"(src));
}
#define CP_COMMIT()  asm volatile("cp.async.commit_group;\n")
#define CP_WAIT(n)   asm volatile("cp.async.wait_group %0;\n" :: "n"(n))

// ---------------- gx GEMM: 128x128 tile, BK=32, 2-stage cp.async --------------
#define PLD 40
#define GX_SMEM (2 * 4 * 128 * PLD * 2)   // 81920 B

__global__ __launch_bounds__(256) void k_gx_gemm() {
    extern __shared__ __nv_bfloat16 smx[];
    const int tid = threadIdx.x;
    const int m0 = blockIdx.x * 128, n0 = blockIdx.y * 128;
    const int wid = tid >> 5, wm = wid & 3, wn = wid >> 2;

    wmma::fragment<wmma::accumulator, 16, 16, 16, float> acc[2][4];
    #pragma unroll
    for (int i = 0; i < 2; i++)
        #pragma unroll
        for (int j = 0; j < 4; j++) wmma::fill_fragment(acc[i][j], 0.0f);

    auto tileptr = [&](int s, int t) { return smx + (size_t)(s * 4 + t) * 128 * PLD; };

    auto issue = [&](int ks, int s) {
        int k0 = ks * 32;
        #pragma unroll
        for (int it = 0; it < 8; it++) {
            int idx = tid + it * 256;        // 0..2047
            int t   = idx >> 9;              // tile 0..3
            int row = (idx >> 2) & 127;
            int ch  = idx & 3;
            const __nv_bfloat16* src;
            if      (t == 0) src = g_xhi    + (size_t)(m0 + row) * KIN + k0 + ch * 8;
            else if (t == 1) src = g_xlo    + (size_t)(m0 + row) * KIN + k0 + ch * 8;
            else if (t == 2) src = g_wih_hi + (size_t)(n0 + row) * KIN + k0 + ch * 8;
            else             src = g_wih_lo + (size_t)(n0 + row) * KIN + k0 + ch * 8;
            cp16(tileptr(s, t) + row * PLD + ch * 8, src);
        }
        CP_COMMIT();
    };

    issue(0, 0);
    for (int ks = 0; ks < 32; ks++) {
        if (ks < 31) { issue(ks + 1, (ks + 1) & 1); CP_WAIT(1); }
        else         { CP_WAIT(0); }
        __syncthreads();
        int s = ks & 1;
        __nv_bfloat16 *Ahi = tileptr(s, 0), *Alo = tileptr(s, 1);
        __nv_bfloat16 *Bhi = tileptr(s, 2), *Blo = tileptr(s, 3);
        #pragma unroll
        for (int kk = 0; kk < 32; kk += 16) {
            wmma::fragment<wmma::matrix_a, 16, 16, 16, __nv_bfloat16, wmma::row_major> a_hi[2], a_lo[2];
            #pragma unroll
            for (int i = 0; i < 2; i++) {
                wmma::load_matrix_sync(a_hi[i], &Ahi[(wm * 32 + i * 16) * PLD + kk], PLD);
                wmma::load_matrix_sync(a_lo[i], &Alo[(wm * 32 + i * 16) * PLD + kk], PLD);
            }
            #pragma unroll
            for (int j = 0; j < 4; j++) {
                wmma::fragment<wmma::matrix_b, 16, 16, 16, __nv_bfloat16, wmma::col_major> b_hi, b_lo;
                wmma::load_matrix_sync(b_hi, &Bhi[(wn * 64 + j * 16) * PLD + kk], PLD);
                wmma::load_matrix_sync(b_lo, &Blo[(wn * 64 + j * 16) * PLD + kk], PLD);
                #pragma unroll
                for (int i = 0; i < 2; i++) {
                    wmma::mma_sync(acc[i][j], a_hi[i], b_hi, acc[i][j]);
                    wmma::mma_sync(acc[i][j], a_hi[i], b_lo, acc[i][j]);
                    wmma::mma_sync(acc[i][j], a_lo[i], b_hi, acc[i][j]);
                }
            }
        }
        __syncthreads();
    }

    #pragma unroll
    for (int i = 0; i < 2; i++)
        #pragma unroll
        for (int j = 0; j < 4; j++) {
            size_t m = (size_t)m0 + wm * 32 + i * 16;
            size_t n = (size_t)n0 + wn * 64 + j * 16;
            wmma::store_matrix_sync(&g_gx[m * G3 + n], acc[i][j], G3, wmma::mem_row_major);
        }
}

// ---------------- persistent GRU recurrence -----------------------------------
#define WS_LDW 516                              // u32 per W smem row (1024 bf16 + 16 pad)
#define PERS_SMEM (2 * 24 * WS_LDW * 4)         // 99072 B

__device__ __forceinline__ void mma16816(float c[4], unsigned a0, unsigned a1,
                                         unsigned a2, unsigned a3,
                                         unsigned b0, unsigned b1) {
    asm volatile(
        "mma.sync.aligned.m16n8k16.row.col.f32.bf16.bf16.f32 "
        "{%0,%1,%2,%3},{%4,%5,%6,%7},{%8,%9},{%0,%1,%2,%3};\n"
        : "+f"(c[0]), "+f"(c[1]), "+f"(c[2]), "+f"(c[3])
        : "r"(a0), "r"(a1), "r"(a2), "r"(a3), "r"(b0), "r"(b1));
}

__device__ __forceinline__ void load_group(const unsigned* __restrict__ hhi,
                                           const unsigned* __restrict__ hlo,
                                           int rA512, int rB512, int gi, int l4,
                                           unsigned R[4][8]) {
    #pragma unroll
    for (int c = 0; c < 4; c++) {
        int wb = gi * 32 + c * 8 + l4;
        R[c][0] = hhi[rA512 + wb];     R[c][1] = hhi[rB512 + wb];
        R[c][2] = hhi[rA512 + wb + 4]; R[c][3] = hhi[rB512 + wb + 4];
        R[c][4] = hlo[rA512 + wb];     R[c][5] = hlo[rB512 + wb];
        R[c][6] = hlo[rA512 + wb + 4]; R[c][7] = hlo[rB512 + wb + 4];
    }
}

__device__ __forceinline__ void mma_group(const unsigned* __restrict__ ws_hi,
                                          const unsigned* __restrict__ ws_lo,
                                          int gi, int l4, int n,
                                          unsigned R[4][8], float acc[3][4]) {
    #pragma unroll
    for (int c = 0; c < 4; c++) {
        int kw = gi * 32 + c * 8;
        #pragma unroll
        for (int g = 0; g < 3; g++) {
            int rowoff = (g * 8 + n) * WS_LDW + kw;
            unsigned bh0 = ws_hi[rowoff + l4],     bh1 = ws_hi[rowoff + 4 + l4];
            unsigned bl0 = ws_lo[rowoff + l4],     bl1 = ws_lo[rowoff + 4 + l4];
            mma16816(acc[g], R[c][0], R[c][1], R[c][2], R[c][3], bh0, bh1);
            mma16816(acc[g], R[c][0], R[c][1], R[c][2], R[c][3], bl0, bl1);
            mma16816(acc[g], R[c][4], R[c][5], R[c][6], R[c][7], bh0, bh1);
        }
    }
}

__device__ __forceinline__ void grid_bar(unsigned target) {
    __threadfence();
    __syncthreads();
    if (threadIdx.x == 0) {
        atomicAdd(&g_count, 1u);
        while (*(volatile unsigned*)&g_count < target) __nanosleep(20);
        __threadfence();
    }
    __syncthreads();
}

__device__ __forceinline__ float sig(float x) { return 1.0f / (1.0f + __expf(-x)); }

__global__ __launch_bounds__(256) void k_gru_persist(
        const float* __restrict__ h0, const float* __restrict__ bih,
        const float* __restrict__ bhh, float* __restrict__ out, int wh)
{
    extern __shared__ unsigned wsm[];
    unsigned* ws_hi = wsm;
    unsigned* ws_lo = wsm + 24 * WS_LDW;

    const int tid = threadIdx.x, w = tid >> 5, l = tid & 31;
    const int l4 = l & 3, n = l >> 2;
    const int j0 = blockIdx.x * 8;

    // load resident W slice (rows: 3 gates x 8 j-cols, each 1024 K)
    const unsigned* whh_hi32 = (const unsigned*)g_whh_hi;
    const unsigned* whh_lo32 = (const unsigned*)g_whh_lo;
    for (int i = tid; i < 24 * 512; i += 256) {
        int rr = i >> 9, kk = i & 511;
        int g = rr >> 3, jr = rr & 7;
        size_t src = (size_t)(g * 1024 + j0 + jr) * 512 + kk;
        ws_hi[rr * WS_LDW + kk] = whh_hi32[src];
        ws_lo[rr * WS_LDW + kk] = whh_lo32[src];
    }

    const int rA = w * 16 + n, rB = rA + 8;
    const int rA512 = rA * 512, rB512 = rB * 512;
    const int jc = j0 + l4 * 2;

    float bi[3][2], bh[3][2];
    #pragma unroll
    for (int g = 0; g < 3; g++) {
        bi[g][0] = bih[g * 1024 + jc]; bi[g][1] = bih[g * 1024 + jc + 1];
        bh[g][0] = bhh[g * 1024 + jc]; bh[g][1] = bhh[g * 1024 + jc + 1];
    }

    // hidden state in registers: 4 cells (rA,jc),(rA,jc+1),(rB,jc),(rB,jc+1)
    float hA0 = h0[rA * H_DIM + jc], hA1 = h0[rA * H_DIM + jc + 1];
    float hB0 = h0[rB * H_DIM + jc], hB1 = h0[rB * H_DIM + jc + 1];

    auto wr_h = [&](unsigned* dhi, unsigned* dlo, int r512, float v0, float v1) {
        __nv_bfloat162 ph, pl;
        ph.x = __float2bfloat16(v0); ph.y = __float2bfloat16(v1);
        pl.x = __float2bfloat16(v0 - __bfloat162float(ph.x));
        pl.y = __float2bfloat16(v1 - __bfloat162float(ph.y));
        dhi[r512 + (jc >> 1)] = *(unsigned*)&ph;
        dlo[r512 + (jc >> 1)] = *(unsigned*)&pl;
    };

    // publish initial split h to buffer 0
    wr_h((unsigned*)g_hhi[0], (unsigned*)g_hlo[0], rA512, hA0, hA1);
    wr_h((unsigned*)g_hhi[0], (unsigned*)g_hlo[0], rB512, hB0, hB1);
    grid_bar(NBLK);

    unsigned tgt = 2 * NBLK;
    for (int t = 0; t < T_STEPS; t++) {
        const unsigned* hhi = (const unsigned*)g_hhi[t & 1];
        const unsigned* hlo = (const unsigned*)g_hlo[t & 1];
        unsigned* nhhi = (unsigned*)g_hhi[(t + 1) & 1];
        unsigned* nhlo = (unsigned*)g_hlo[(t + 1) & 1];
        const float* gx = g_gx + (size_t)t * B_SZ * G3;

        // prefetch input-side preacts (DRAM; consumed ~9K cycles later)
        float2 xA[3], xB[3];
        #pragma unroll
        for (int g = 0; g < 3; g++) {
            xA[g] = *(const float2*)&gx[(size_t)rA * G3 + g * 1024 + jc];
            xB[g] = *(const float2*)&gx[(size_t)rB * G3 + g * 1024 + jc];
        }

        float acc[3][4];
        #pragma unroll
        for (int g = 0; g < 3; g++)
            #pragma unroll
            for (int c = 0; c < 4; c++) acc[g][c] = 0.0f;

        unsigned Ra[4][8], Rb[4][8];
        load_group(hhi, hlo, rA512, rB512, 0, l4, Ra);
        #pragma unroll 1
        for (int gi = 0; gi < 16; gi += 2) {
            if (gi + 1 < 16) load_group(hhi, hlo, rA512, rB512, gi + 1, l4, Rb);
            mma_group(ws_hi, ws_lo, gi, l4, n, Ra, acc);
            if (gi + 2 < 16) load_group(hhi, hlo, rA512, rB512, gi + 2, l4, Ra);
            if (gi + 1 < 16) mma_group(ws_hi, ws_lo, gi + 1, l4, n, Rb, acc);
        }

        // gating (cells: 0:(rA,jc) 1:(rA,jc+1) 2:(rB,jc) 3:(rB,jc+1))
        {
            float r0 = sig(xA[0].x + bi[0][0] + acc[0][0] + bh[0][0]);
            float z0 = sig(xA[1].x + bi[1][0] + acc[1][0] + bh[1][0]);
            float n0 = tanhf(xA[2].x + bi[2][0] + r0 * (acc[2][0] + bh[2][0]));
            hA0 = (1.0f - z0) * n0 + z0 * hA0;
            float r1 = sig(xA[0].y + bi[0][1] + acc[0][1] + bh[0][1]);
            float z1 = sig(xA[1].y + bi[1][1] + acc[1][1] + bh[1][1]);
            float n1 = tanhf(xA[2].y + bi[2][1] + r1 * (acc[2][1] + bh[2][1]));
            hA1 = (1.0f - z1) * n1 + z1 * hA1;
            float r2 = sig(xB[0].x + bi[0][0] + acc[0][2] + bh[0][0]);
            float z2 = sig(xB[1].x + bi[1][0] + acc[1][2] + bh[1][0]);
            float n2 = tanhf(xB[2].x + bi[2][0] + r2 * (acc[2][2] + bh[2][0]));
            hB0 = (1.0f - z2) * n2 + z2 * hB0;
            float r3 = sig(xB[0].y + bi[0][1] + acc[0][3] + bh[0][1]);
            float z3 = sig(xB[1].y + bi[1][1] + acc[1][3] + bh[1][1]);
            float n3 = tanhf(xB[2].y + bi[2][1] + r3 * (acc[2][3] + bh[2][1]));
            hB1 = (1.0f - z3) * n3 + z3 * hB1;
        }

        // outputs
        float2 oA = {hA0, hA1}, oB = {hB0, hB1};
        *(float2*)&out[((size_t)t * B_SZ + rA) * H_DIM + jc] = oA;
        *(float2*)&out[((size_t)t * B_SZ + rB) * H_DIM + jc] = oB;
        wr_h(nhhi, nhlo, rA512, hA0, hA1);
        wr_h(nhhi, nhlo, rB512, hB0, hB1);
        if (t == T_STEPS - 1 && wh) {
            *(float2*)&out[(size_t)M_TOT * H_DIM + (size_t)rA * H_DIM + jc] = oA;
            *(float2*)&out[(size_t)M_TOT * H_DIM + (size_t)rB * H_DIM + jc] = oB;
        }

        grid_bar(tgt);
        tgt += NBLK;
    }
}

// ---------------- launch ------------------------------------------------------
extern "C" void kernel_launch(void* const* d_in, const int* in_sizes, int n_in,
                              void* d_out, int out_size) {
    const float* seq  = (const float*)d_in[0];
    const float* word = (const float*)d_in[1];
    const float* h0   = (const float*)d_in[2];
    const float* wih  = (const float*)d_in[3];
    const float* whh  = (const float*)d_in[4];
    const float* bih  = (const float*)d_in[5];
    const float* bhh  = (const float*)d_in[6];
    float* out = (float*)d_out;
    (void)in_sizes; (void)n_in;

    cudaFuncSetAttribute(k_gx_gemm, cudaFuncAttributeMaxDynamicSharedMemorySize, GX_SMEM);
    cudaFuncSetAttribute(k_gru_persist, cudaFuncAttributeMaxDynamicSharedMemorySize, PERS_SMEM);

    const int hidden_ok = (out_size >= T_STEPS * B_SZ * H_DIM + B_SZ * H_DIM) ? 1 : 0;

    k_init<<<1, 32>>>();
    k_split_whh<<<(G3 * H_DIM + 255) / 256, 256>>>(whh);
    k_split_wih<<<(G3 * KIN + 255) / 256, 256>>>(wih);
    k_split_x<<<(int)(((size_t)M_TOT * KIN / 4 + 255) / 256), 256>>>(seq, word);

    k_gx_gemm<<<dim3(M_TOT / 128, G3 / 128), 256, GX_SMEM>>>();

    k_gru_persist<<<NBLK, 256, PERS_SMEM>>>(h0, bih, bhh, out, hidden_ok);
}